// round 1
// baseline (speedup 1.0000x reference)
#include <cuda_runtime.h>
#include <cstddef>

#define GRIDS 64
#define FEAT 2
#define RES 64
#define R3 (RES*RES*RES)
#define NPL 64
#define NPTS 262144

// Transposed grids: (g, z, y, x, {f0,f1}) as float2. 64 * 262144 * 8B = 134MB.
__device__ float2 g_grids_t[(size_t)GRIDS * R3];

// ---------------------------------------------------------------------------
// Kernel 1: transpose (G,F,R,R,R) -> (G,R,R,R,F) so each corner's two
// features arrive in a single 8-byte load.
// ---------------------------------------------------------------------------
__global__ void transpose_grids_kernel(const float* __restrict__ grids) {
    int tid = blockIdx.x * blockDim.x + threadIdx.x;   // 0 .. G*R3-1 (16.7M)
    if (tid >= GRIDS * R3) return;
    int g = tid >> 18;          // / R3  (R3 = 2^18)
    int v = tid & (R3 - 1);
    float f0 = grids[(size_t)(2 * g)     * R3 + v];
    float f1 = grids[(size_t)(2 * g + 1) * R3 + v];
    g_grids_t[tid] = make_float2(f0, f1);
}

// ---------------------------------------------------------------------------
// Kernel 2: fully fused  transform -> trilinear sample -> 3-layer MLP.
// One thread = one point. Weights + transforms staged in dynamic SMEM.
// SMEM float layout:
//   [0     .. 8192)  W0  (128 x 64)
//   [8192  .. 12288) W1  (64 x 64)
//   [12288 .. 13056) M   (64 grids x 12: rows 0..2 of 4x4)
//   [13056 .. 13120) b0
//   [13120 .. 13184) b1
//   [13184 .. 13248) W2
//   [13248 .. 13249) b2
// ---------------------------------------------------------------------------
#define SMEM_FLOATS 13249

extern __shared__ float smem[];

__global__ void __launch_bounds__(128)
fused_amgsrn_kernel(const float* __restrict__ x,
                    const float* __restrict__ Mmat,
                    const float* __restrict__ W0g,
                    const float* __restrict__ b0g,
                    const float* __restrict__ W1g,
                    const float* __restrict__ b1g,
                    const float* __restrict__ W2g,
                    const float* __restrict__ b2g,
                    float* __restrict__ out)
{
    float* sW0 = smem;
    float* sW1 = smem + 8192;
    float* sM  = smem + 12288;
    float* sb0 = smem + 13056;
    float* sb1 = smem + 13120;
    float* sW2 = smem + 13184;
    float* sb2 = smem + 13248;

    const int tid = threadIdx.x;

    for (int i = tid; i < 8192; i += 128) sW0[i] = W0g[i];
    for (int i = tid; i < 4096; i += 128) sW1[i] = W1g[i];
    for (int i = tid; i < 768;  i += 128) {
        int g = i / 12, r = i % 12;            // rows 0..2, cols 0..3
        sM[i] = Mmat[g * 16 + r];
    }
    if (tid < 64) {
        sb0[tid] = b0g[tid];
        sb1[tid] = b1g[tid];
        sW2[tid] = W2g[tid];
    }
    if (tid == 0) sb2[0] = b2g[0];
    __syncthreads();

    const int n = blockIdx.x * 128 + tid;
    const float px = x[3 * n + 0];
    const float py = x[3 * n + 1];
    const float pz = x[3 * n + 2];

    float h[NPL];
    #pragma unroll
    for (int j = 0; j < NPL; j++) h[j] = 0.0f;

    for (int g = 0; g < GRIDS; g++) {
        const float* Mg = sM + g * 12;
        // tp = (M @ [x,1])[:3]
        float tx = fmaf(Mg[0], px, fmaf(Mg[1], py, fmaf(Mg[2],  pz, Mg[3])));
        float ty = fmaf(Mg[4], px, fmaf(Mg[5], py, fmaf(Mg[6],  pz, Mg[7])));
        float tz = fmaf(Mg[8], px, fmaf(Mg[9], py, fmaf(Mg[10], pz, Mg[11])));

        // grid coords: ix uses x (fastest dim), iz uses z (slowest)
        float ix = fmaf(tx, 31.5f, 31.5f);
        float iy = fmaf(ty, 31.5f, 31.5f);
        float iz = fmaf(tz, 31.5f, 31.5f);

        float xf = floorf(ix), yf = floorf(iy), zf = floorf(iz);
        float wx = ix - xf,    wy = iy - yf,    wz = iz - zf;
        int x0 = (int)xf, y0 = (int)yf, z0 = (int)zf;

        // per-axis weights with zero-padding validity folded in
        float wx0 = (x0 >= 0  && x0 <  RES    ) ? (1.0f - wx) : 0.0f;
        float wx1 = (x0 >= -1 && x0 <  RES - 1) ? wx          : 0.0f;
        float wy0 = (y0 >= 0  && y0 <  RES    ) ? (1.0f - wy) : 0.0f;
        float wy1 = (y0 >= -1 && y0 <  RES - 1) ? wy          : 0.0f;
        float wz0 = (z0 >= 0  && z0 <  RES    ) ? (1.0f - wz) : 0.0f;
        float wz1 = (z0 >= -1 && z0 <  RES - 1) ? wz          : 0.0f;

        int xc0 = min(max(x0, 0), RES - 1),  xc1 = min(max(x0 + 1, 0), RES - 1);
        int yc0 = min(max(y0, 0), RES - 1),  yc1 = min(max(y0 + 1, 0), RES - 1);
        int zc0 = min(max(z0, 0), RES - 1),  zc1 = min(max(z0 + 1, 0), RES - 1);

        const float2* base = g_grids_t + (size_t)g * R3;
        int r00 = (zc0 * RES + yc0) * RES;
        int r01 = (zc0 * RES + yc1) * RES;
        int r10 = (zc1 * RES + yc0) * RES;
        int r11 = (zc1 * RES + yc1) * RES;

        float2 c000 = __ldg(base + r00 + xc0);
        float2 c001 = __ldg(base + r00 + xc1);
        float2 c010 = __ldg(base + r01 + xc0);
        float2 c011 = __ldg(base + r01 + xc1);
        float2 c100 = __ldg(base + r10 + xc0);
        float2 c101 = __ldg(base + r10 + xc1);
        float2 c110 = __ldg(base + r11 + xc0);
        float2 c111 = __ldg(base + r11 + xc1);

        float w00 = wz0 * wy0, w01 = wz0 * wy1;
        float w10 = wz1 * wy0, w11 = wz1 * wy1;
        float w000 = w00 * wx0, w001 = w00 * wx1;
        float w010 = w01 * wx0, w011 = w01 * wx1;
        float w100 = w10 * wx0, w101 = w10 * wx1;
        float w110 = w11 * wx0, w111 = w11 * wx1;

        float f0 = w000 * c000.x;
        float f1 = w000 * c000.y;
        f0 = fmaf(w001, c001.x, f0);  f1 = fmaf(w001, c001.y, f1);
        f0 = fmaf(w010, c010.x, f0);  f1 = fmaf(w010, c010.y, f1);
        f0 = fmaf(w011, c011.x, f0);  f1 = fmaf(w011, c011.y, f1);
        f0 = fmaf(w100, c100.x, f0);  f1 = fmaf(w100, c100.y, f1);
        f0 = fmaf(w101, c101.x, f0);  f1 = fmaf(w101, c101.y, f1);
        f0 = fmaf(w110, c110.x, f0);  f1 = fmaf(w110, c110.y, f1);
        f0 = fmaf(w111, c111.x, f0);  f1 = fmaf(w111, c111.y, f1);

        // layer 0 accumulation: h += f0 * W0[2g,:] + f1 * W0[2g+1,:]
        const float4* r0v = (const float4*)(sW0 + (2 * g)     * NPL);
        const float4* r1v = (const float4*)(sW0 + (2 * g + 1) * NPL);
        #pragma unroll
        for (int jj = 0; jj < 16; jj++) {
            float4 a = r0v[jj];
            float4 b = r1v[jj];
            h[4*jj+0] = fmaf(f0, a.x, fmaf(f1, b.x, h[4*jj+0]));
            h[4*jj+1] = fmaf(f0, a.y, fmaf(f1, b.y, h[4*jj+1]));
            h[4*jj+2] = fmaf(f0, a.z, fmaf(f1, b.z, h[4*jj+2]));
            h[4*jj+3] = fmaf(f0, a.w, fmaf(f1, b.w, h[4*jj+3]));
        }
    }

    // bias + relu for layer 0
    #pragma unroll
    for (int j = 0; j < NPL; j++) h[j] = fmaxf(h[j] + sb0[j], 0.0f);

    // layers 1+2, processed in two 32-wide halves to cap live registers
    float o = sb2[0];
    #pragma unroll
    for (int half = 0; half < 2; half++) {
        float acc[32];
        #pragma unroll
        for (int j = 0; j < 32; j++) acc[j] = sb1[half * 32 + j];
        #pragma unroll
        for (int k = 0; k < NPL; k++) {
            float hk = h[k];
            const float4* wr = (const float4*)(sW1 + k * NPL + half * 32);
            #pragma unroll
            for (int jj = 0; jj < 8; jj++) {
                float4 w = wr[jj];
                acc[4*jj+0] = fmaf(hk, w.x, acc[4*jj+0]);
                acc[4*jj+1] = fmaf(hk, w.y, acc[4*jj+1]);
                acc[4*jj+2] = fmaf(hk, w.z, acc[4*jj+2]);
                acc[4*jj+3] = fmaf(hk, w.w, acc[4*jj+3]);
            }
        }
        #pragma unroll
        for (int j = 0; j < 32; j++)
            o = fmaf(fmaxf(acc[j], 0.0f), sW2[half * 32 + j], o);
    }

    out[n] = o;
}

// ---------------------------------------------------------------------------
// Launch. Inputs (metadata order):
//  0: x (N,3) f32            1: transformation_matrices (G,4,4) f32
//  2: feature_grids (G,F,R,R,R) f32
//  3: W0 (128,64)  4: b0 (64)  5: W1 (64,64)  6: b1 (64)  7: W2 (64,1) 8: b2 (1)
// ---------------------------------------------------------------------------
extern "C" void kernel_launch(void* const* d_in, const int* in_sizes, int n_in,
                              void* d_out, int out_size)
{
    const float* x   = (const float*)d_in[0];
    const float* M   = (const float*)d_in[1];
    const float* fg  = (const float*)d_in[2];
    const float* W0  = (const float*)d_in[3];
    const float* b0  = (const float*)d_in[4];
    const float* W1  = (const float*)d_in[5];
    const float* b1  = (const float*)d_in[6];
    const float* W2  = (const float*)d_in[7];
    const float* b2  = (const float*)d_in[8];
    float* out = (float*)d_out;

    // 1) transpose grids into (g,z,y,x,f) float2
    {
        int total = GRIDS * R3;
        int threads = 256;
        int blocks = (total + threads - 1) / threads;
        transpose_grids_kernel<<<blocks, threads>>>(fg);
    }

    // 2) fused pipeline
    {
        size_t smem_bytes = (size_t)SMEM_FLOATS * sizeof(float);
        cudaFuncSetAttribute(fused_amgsrn_kernel,
                             cudaFuncAttributeMaxDynamicSharedMemorySize,
                             (int)smem_bytes);
        int blocks = NPTS / 128;
        fused_amgsrn_kernel<<<blocks, 128, smem_bytes>>>(
            x, M, W0, b0, W1, b1, W2, b2, out);
    }
}

// round 2
// speedup vs baseline: 1.1450x; 1.1450x over previous
#include <cuda_runtime.h>
#include <cstddef>

#define GRIDS 64
#define FEAT 2
#define RES 64
#define R3 (RES*RES*RES)
#define NPL 64
#define NPTS 262144
#define NBINS 32768   // 5 bits per axis Morton

// Transposed grids: (g, z, y, x, {f0,f1}) as float2. 134MB.
__device__ float2 g_grids_t[(size_t)GRIDS * R3];
// Sorting scratch
__device__ int g_keys[NPTS];
__device__ int g_perm[NPTS];
__device__ int g_hist[NBINS];
__device__ int g_cursor[NBINS];

// ---------------------------------------------------------------------------
// Kernel 1: transpose (G,F,R,R,R) -> (G,R,R,R,F) float2
// ---------------------------------------------------------------------------
__global__ void transpose_grids_kernel(const float* __restrict__ grids) {
    int tid = blockIdx.x * blockDim.x + threadIdx.x;
    if (tid >= GRIDS * R3) return;
    int g = tid >> 18;
    int v = tid & (R3 - 1);
    float f0 = grids[(size_t)(2 * g)     * R3 + v];
    float f1 = grids[(size_t)(2 * g + 1) * R3 + v];
    g_grids_t[tid] = make_float2(f0, f1);
}

// ---------------------------------------------------------------------------
// Morton sort pipeline
// ---------------------------------------------------------------------------
__global__ void zero_hist_kernel() {
    int i = blockIdx.x * blockDim.x + threadIdx.x;
    if (i < NBINS) g_hist[i] = 0;
}

__device__ __forceinline__ unsigned part1by2(unsigned v) {
    v = (v * 0x00010001u) & 0xFF0000FFu;
    v = (v * 0x00000101u) & 0x0F00F00Fu;
    v = (v * 0x00000011u) & 0xC30C30C3u;
    v = (v * 0x00000005u) & 0x49249249u;
    return v;
}

__global__ void keys_kernel(const float* __restrict__ x) {
    int i = blockIdx.x * blockDim.x + threadIdx.x;
    if (i >= NPTS) return;
    float px = x[3 * i + 0];
    float py = x[3 * i + 1];
    float pz = x[3 * i + 2];
    int qx = min(max((int)((px + 1.0f) * 16.0f), 0), 31);
    int qy = min(max((int)((py + 1.0f) * 16.0f), 0), 31);
    int qz = min(max((int)((pz + 1.0f) * 16.0f), 0), 31);
    int key = (int)(part1by2((unsigned)qx)
                  | (part1by2((unsigned)qy) << 1)
                  | (part1by2((unsigned)qz) << 2));
    g_keys[i] = key;
    atomicAdd(&g_hist[key], 1);
}

// single block, 1024 threads, 32 bins each -> exclusive scan into g_cursor
__global__ void scan_kernel() {
    __shared__ int sums[1024];
    int t = threadIdx.x;
    int base = t * 32;
    int local[32];
    int s = 0;
    #pragma unroll
    for (int i = 0; i < 32; i++) { local[i] = g_hist[base + i]; s += local[i]; }
    sums[t] = s;
    __syncthreads();
    for (int off = 1; off < 1024; off <<= 1) {
        int v = (t >= off) ? sums[t - off] : 0;
        __syncthreads();
        sums[t] += v;
        __syncthreads();
    }
    int excl = sums[t] - s;
    #pragma unroll
    for (int i = 0; i < 32; i++) { g_cursor[base + i] = excl; excl += local[i]; }
}

__global__ void scatter_kernel() {
    int i = blockIdx.x * blockDim.x + threadIdx.x;
    if (i >= NPTS) return;
    int key = g_keys[i];
    int p = atomicAdd(&g_cursor[key], 1);
    g_perm[p] = i;
}

// ---------------------------------------------------------------------------
// Kernel: fully fused  transform -> trilinear sample -> 3-layer MLP,
// operating on Morton-sorted point order (gather via g_perm, scatter out).
// SMEM float layout:
//   [0..8192) W0 | [8192..12288) W1 | [12288..13056) M(64x12)
//   [13056..13120) b0 | [13120..13184) b1 | [13184..13248) W2 | [13248] b2
// ---------------------------------------------------------------------------
#define SMEM_FLOATS 13249

extern __shared__ float smem[];

__global__ void __launch_bounds__(128)
fused_amgsrn_kernel(const float* __restrict__ x,
                    const float* __restrict__ Mmat,
                    const float* __restrict__ W0g,
                    const float* __restrict__ b0g,
                    const float* __restrict__ W1g,
                    const float* __restrict__ b1g,
                    const float* __restrict__ W2g,
                    const float* __restrict__ b2g,
                    float* __restrict__ out)
{
    float* sW0 = smem;
    float* sW1 = smem + 8192;
    float* sM  = smem + 12288;
    float* sb0 = smem + 13056;
    float* sb1 = smem + 13120;
    float* sW2 = smem + 13184;
    float* sb2 = smem + 13248;

    const int tid = threadIdx.x;

    for (int i = tid; i < 8192; i += 128) sW0[i] = W0g[i];
    for (int i = tid; i < 4096; i += 128) sW1[i] = W1g[i];
    for (int i = tid; i < 768;  i += 128) {
        int g = i / 12, r = i % 12;
        sM[i] = Mmat[g * 16 + r];
    }
    if (tid < 64) {
        sb0[tid] = b0g[tid];
        sb1[tid] = b1g[tid];
        sW2[tid] = W2g[tid];
    }
    if (tid == 0) sb2[0] = b2g[0];
    __syncthreads();

    const int slot = blockIdx.x * 128 + tid;
    const int n = g_perm[slot];
    const float px = x[3 * n + 0];
    const float py = x[3 * n + 1];
    const float pz = x[3 * n + 2];

    float h[NPL];
    #pragma unroll
    for (int j = 0; j < NPL; j++) h[j] = 0.0f;

    for (int g = 0; g < GRIDS; g++) {
        const float* Mg = sM + g * 12;
        float tx = fmaf(Mg[0], px, fmaf(Mg[1], py, fmaf(Mg[2],  pz, Mg[3])));
        float ty = fmaf(Mg[4], px, fmaf(Mg[5], py, fmaf(Mg[6],  pz, Mg[7])));
        float tz = fmaf(Mg[8], px, fmaf(Mg[9], py, fmaf(Mg[10], pz, Mg[11])));

        float ix = fmaf(tx, 31.5f, 31.5f);
        float iy = fmaf(ty, 31.5f, 31.5f);
        float iz = fmaf(tz, 31.5f, 31.5f);

        float xf = floorf(ix), yf = floorf(iy), zf = floorf(iz);
        float wx = ix - xf,    wy = iy - yf,    wz = iz - zf;
        int x0 = (int)xf, y0 = (int)yf, z0 = (int)zf;

        float wx0 = (x0 >= 0  && x0 <  RES    ) ? (1.0f - wx) : 0.0f;
        float wx1 = (x0 >= -1 && x0 <  RES - 1) ? wx          : 0.0f;
        float wy0 = (y0 >= 0  && y0 <  RES    ) ? (1.0f - wy) : 0.0f;
        float wy1 = (y0 >= -1 && y0 <  RES - 1) ? wy          : 0.0f;
        float wz0 = (z0 >= 0  && z0 <  RES    ) ? (1.0f - wz) : 0.0f;
        float wz1 = (z0 >= -1 && z0 <  RES - 1) ? wz          : 0.0f;

        int xc0 = min(max(x0, 0), RES - 1),  xc1 = min(max(x0 + 1, 0), RES - 1);
        int yc0 = min(max(y0, 0), RES - 1),  yc1 = min(max(y0 + 1, 0), RES - 1);
        int zc0 = min(max(z0, 0), RES - 1),  zc1 = min(max(z0 + 1, 0), RES - 1);

        const float2* base = g_grids_t + (size_t)g * R3;
        int r00 = (zc0 * RES + yc0) * RES;
        int r01 = (zc0 * RES + yc1) * RES;
        int r10 = (zc1 * RES + yc0) * RES;
        int r11 = (zc1 * RES + yc1) * RES;

        float2 c000 = __ldg(base + r00 + xc0);
        float2 c001 = __ldg(base + r00 + xc1);
        float2 c010 = __ldg(base + r01 + xc0);
        float2 c011 = __ldg(base + r01 + xc1);
        float2 c100 = __ldg(base + r10 + xc0);
        float2 c101 = __ldg(base + r10 + xc1);
        float2 c110 = __ldg(base + r11 + xc0);
        float2 c111 = __ldg(base + r11 + xc1);

        float w00 = wz0 * wy0, w01 = wz0 * wy1;
        float w10 = wz1 * wy0, w11 = wz1 * wy1;
        float w000 = w00 * wx0, w001 = w00 * wx1;
        float w010 = w01 * wx0, w011 = w01 * wx1;
        float w100 = w10 * wx0, w101 = w10 * wx1;
        float w110 = w11 * wx0, w111 = w11 * wx1;

        float f0 = w000 * c000.x;
        float f1 = w000 * c000.y;
        f0 = fmaf(w001, c001.x, f0);  f1 = fmaf(w001, c001.y, f1);
        f0 = fmaf(w010, c010.x, f0);  f1 = fmaf(w010, c010.y, f1);
        f0 = fmaf(w011, c011.x, f0);  f1 = fmaf(w011, c011.y, f1);
        f0 = fmaf(w100, c100.x, f0);  f1 = fmaf(w100, c100.y, f1);
        f0 = fmaf(w101, c101.x, f0);  f1 = fmaf(w101, c101.y, f1);
        f0 = fmaf(w110, c110.x, f0);  f1 = fmaf(w110, c110.y, f1);
        f0 = fmaf(w111, c111.x, f0);  f1 = fmaf(w111, c111.y, f1);

        const float4* r0v = (const float4*)(sW0 + (2 * g)     * NPL);
        const float4* r1v = (const float4*)(sW0 + (2 * g + 1) * NPL);
        #pragma unroll
        for (int jj = 0; jj < 16; jj++) {
            float4 a = r0v[jj];
            float4 b = r1v[jj];
            h[4*jj+0] = fmaf(f0, a.x, fmaf(f1, b.x, h[4*jj+0]));
            h[4*jj+1] = fmaf(f0, a.y, fmaf(f1, b.y, h[4*jj+1]));
            h[4*jj+2] = fmaf(f0, a.z, fmaf(f1, b.z, h[4*jj+2]));
            h[4*jj+3] = fmaf(f0, a.w, fmaf(f1, b.w, h[4*jj+3]));
        }
    }

    #pragma unroll
    for (int j = 0; j < NPL; j++) h[j] = fmaxf(h[j] + sb0[j], 0.0f);

    float o = sb2[0];
    #pragma unroll
    for (int half = 0; half < 2; half++) {
        float acc[32];
        #pragma unroll
        for (int j = 0; j < 32; j++) acc[j] = sb1[half * 32 + j];
        #pragma unroll
        for (int k = 0; k < NPL; k++) {
            float hk = h[k];
            const float4* wr = (const float4*)(sW1 + k * NPL + half * 32);
            #pragma unroll
            for (int jj = 0; jj < 8; jj++) {
                float4 w = wr[jj];
                acc[4*jj+0] = fmaf(hk, w.x, acc[4*jj+0]);
                acc[4*jj+1] = fmaf(hk, w.y, acc[4*jj+1]);
                acc[4*jj+2] = fmaf(hk, w.z, acc[4*jj+2]);
                acc[4*jj+3] = fmaf(hk, w.w, acc[4*jj+3]);
            }
        }
        #pragma unroll
        for (int j = 0; j < 32; j++)
            o = fmaf(fmaxf(acc[j], 0.0f), sW2[half * 32 + j], o);
    }

    out[n] = o;
}

// ---------------------------------------------------------------------------
extern "C" void kernel_launch(void* const* d_in, const int* in_sizes, int n_in,
                              void* d_out, int out_size)
{
    const float* x   = (const float*)d_in[0];
    const float* M   = (const float*)d_in[1];
    const float* fg  = (const float*)d_in[2];
    const float* W0  = (const float*)d_in[3];
    const float* b0  = (const float*)d_in[4];
    const float* W1  = (const float*)d_in[5];
    const float* b1  = (const float*)d_in[6];
    const float* W2  = (const float*)d_in[7];
    const float* b2  = (const float*)d_in[8];
    float* out = (float*)d_out;

    // grid transpose (independent of the sort pipeline)
    {
        int total = GRIDS * R3;
        transpose_grids_kernel<<<(total + 255) / 256, 256>>>(fg);
    }

    // Morton counting sort of points
    zero_hist_kernel<<<NBINS / 256, 256>>>();
    keys_kernel<<<NPTS / 256, 256>>>(x);
    scan_kernel<<<1, 1024>>>();
    scatter_kernel<<<NPTS / 256, 256>>>();

    // fused pipeline on sorted order
    {
        size_t smem_bytes = (size_t)SMEM_FLOATS * sizeof(float);
        cudaFuncSetAttribute(fused_amgsrn_kernel,
                             cudaFuncAttributeMaxDynamicSharedMemorySize,
                             (int)smem_bytes);
        fused_amgsrn_kernel<<<NPTS / 128, 128, smem_bytes>>>(
            x, M, W0, b0, W1, b1, W2, b2, out);
    }
}

// round 5
// speedup vs baseline: 1.6171x; 1.4123x over previous
#include <cuda_runtime.h>
#include <cuda_bf16.h>
#include <cstdint>
#include <cstddef>

#define GRIDS 64
#define RES 64
#define R3 (RES*RES*RES)
#define NPTS 262144
#define NBINS 32768

// ---------------------------------------------------------------------------
// Device globals
// ---------------------------------------------------------------------------
__device__ float2 g_grids_t[(size_t)GRIDS * R3];           // (g,z,y,x,{f0,f1})
__device__ int g_keys[NPTS];
__device__ int g_perm[NPTS];
__device__ float4 g_xs4[NPTS];                             // permuted points
__device__ __align__(16) int g_hist[NBINS];
__device__ __align__(16) int g_cursor[NBINS];
__device__ __nv_bfloat16 g_W0T_hi[64 * 128];               // [n][k]
__device__ __nv_bfloat16 g_W0T_lo[64 * 128];
__device__ __nv_bfloat16 g_W1T_hi[64 * 64];
__device__ __nv_bfloat16 g_W1T_lo[64 * 64];

// ---------------------------------------------------------------------------
// Kernel: prep weights (bf16 hi/lo, transposed to [n][k]) + zero histogram
// ---------------------------------------------------------------------------
__global__ void prep_weights(const float* __restrict__ W0,
                             const float* __restrict__ W1) {
    int tid = blockIdx.x * blockDim.x + threadIdx.x;   // 8192 threads
    ((int4*)g_hist)[tid] = make_int4(0, 0, 0, 0);      // NBINS/4 = 8192
    {
        int k = tid >> 6, n = tid & 63;
        float w = W0[tid];
        __nv_bfloat16 hi = __float2bfloat16(w);
        g_W0T_hi[n * 128 + k] = hi;
        g_W0T_lo[n * 128 + k] = __float2bfloat16(w - __bfloat162float(hi));
    }
    if (tid < 4096) {
        int k = tid >> 6, n = tid & 63;
        float w = W1[tid];
        __nv_bfloat16 hi = __float2bfloat16(w);
        g_W1T_hi[n * 64 + k] = hi;
        g_W1T_lo[n * 64 + k] = __float2bfloat16(w - __bfloat162float(hi));
    }
}

// ---------------------------------------------------------------------------
// Kernel: transpose grids (G,F,R,R,R) -> (G,R,R,R,F) float2, vectorized
// ---------------------------------------------------------------------------
__global__ void transpose_grids_kernel(const float* __restrict__ grids) {
    int tid = blockIdx.x * blockDim.x + threadIdx.x;   // G*R3/4 threads
    if (tid >= GRIDS * R3 / 4) return;
    int g = tid >> 16;
    int v4 = tid & 65535;
    float4 f0 = *(const float4*)(grids + (size_t)(2 * g) * R3 + (size_t)v4 * 4);
    float4 f1 = *(const float4*)(grids + (size_t)(2 * g + 1) * R3 + (size_t)v4 * 4);
    float4* d4 = (float4*)(g_grids_t + (size_t)g * R3 + (size_t)v4 * 4);
    d4[0] = make_float4(f0.x, f1.x, f0.y, f1.y);
    d4[1] = make_float4(f0.z, f1.z, f0.w, f1.w);
}

// ---------------------------------------------------------------------------
// Morton sort
// ---------------------------------------------------------------------------
__device__ __forceinline__ unsigned part1by2(unsigned v) {
    v = (v * 0x00010001u) & 0xFF0000FFu;
    v = (v * 0x00000101u) & 0x0F00F00Fu;
    v = (v * 0x00000011u) & 0xC30C30C3u;
    v = (v * 0x00000005u) & 0x49249249u;
    return v;
}

__global__ void keys_kernel(const float* __restrict__ x) {
    int i = blockIdx.x * blockDim.x + threadIdx.x;
    if (i >= NPTS) return;
    float px = x[3 * i + 0], py = x[3 * i + 1], pz = x[3 * i + 2];
    int qx = min(max((int)((px + 1.0f) * 16.0f), 0), 31);
    int qy = min(max((int)((py + 1.0f) * 16.0f), 0), 31);
    int qz = min(max((int)((pz + 1.0f) * 16.0f), 0), 31);
    int key = (int)(part1by2((unsigned)qx) | (part1by2((unsigned)qy) << 1)
                  | (part1by2((unsigned)qz) << 2));
    g_keys[i] = key;
    atomicAdd(&g_hist[key], 1);
}

// warp-shuffle hierarchical scan, 1 block x 1024 threads, 32 bins/thread
__global__ void scan_kernel() {
    __shared__ int wsum[32];
    int t = threadIdx.x, lane = t & 31, wid = t >> 5;
    const int4* H = (const int4*)(g_hist + t * 32);
    int v[32];
    int s = 0;
    #pragma unroll
    for (int i = 0; i < 8; i++) {
        int4 q = H[i];
        v[4*i] = q.x; v[4*i+1] = q.y; v[4*i+2] = q.z; v[4*i+3] = q.w;
        s += q.x + q.y + q.z + q.w;
    }
    int incl = s;
    #pragma unroll
    for (int o = 1; o < 32; o <<= 1) {
        int u = __shfl_up_sync(0xffffffffu, incl, o);
        if (lane >= o) incl += u;
    }
    if (lane == 31) wsum[wid] = incl;
    __syncthreads();
    if (wid == 0) {
        int ws = wsum[lane];
        int wincl = ws;
        #pragma unroll
        for (int o = 1; o < 32; o <<= 1) {
            int u = __shfl_up_sync(0xffffffffu, wincl, o);
            if (lane >= o) wincl += u;
        }
        wsum[lane] = wincl - ws;
    }
    __syncthreads();
    int excl = wsum[wid] + incl - s;
    int4* C = (int4*)(g_cursor + t * 32);
    #pragma unroll
    for (int i = 0; i < 8; i++) {
        int c0 = excl;            excl += v[4*i];
        int c1 = excl;            excl += v[4*i+1];
        int c2 = excl;            excl += v[4*i+2];
        int c3 = excl;            excl += v[4*i+3];
        C[i] = make_int4(c0, c1, c2, c3);
    }
}

__global__ void scatter_kernel(const float* __restrict__ x) {
    int i = blockIdx.x * blockDim.x + threadIdx.x;
    if (i >= NPTS) return;
    int p = atomicAdd(&g_cursor[g_keys[i]], 1);
    g_perm[p] = i;
    g_xs4[p] = make_float4(x[3 * i], x[3 * i + 1], x[3 * i + 2], 0.0f);
}

// ---------------------------------------------------------------------------
// mma.sync bf16 helper (baseline PTX, works on plain sm_100 target)
// ---------------------------------------------------------------------------
__device__ __forceinline__ void mma_bf16(float d[4],
                                         uint32_t a0, uint32_t a1,
                                         uint32_t a2, uint32_t a3,
                                         uint32_t b0, uint32_t b1) {
    asm volatile(
        "mma.sync.aligned.m16n8k16.row.col.f32.bf16.bf16.f32 "
        "{%0,%1,%2,%3}, {%4,%5,%6,%7}, {%8,%9}, {%0,%1,%2,%3};"
        : "+f"(d[0]), "+f"(d[1]), "+f"(d[2]), "+f"(d[3])
        : "r"(a0), "r"(a1), "r"(a2), "r"(a3), "r"(b0), "r"(b1));
}

__device__ __forceinline__ uint32_t pack2(__nv_bfloat16 a, __nv_bfloat16 b) {
    __nv_bfloat162 t; t.x = a; t.y = b;
    return *(uint32_t*)&t;
}

// ---------------------------------------------------------------------------
// Mega kernel: sample -> SMEM bf16 hi/lo A -> mma.sync layer0 -> relu ->
// layer1 -> relu -> dot W2. 256 points / CTA, 512 threads, 16 warps.
// SMEM (bytes), A row stride = 264 (128 bf16 padded):
// ---------------------------------------------------------------------------
#define ASTR 264
#define OFF_A_HI  0
#define OFF_A_LO  (OFF_A_HI + 256 * ASTR)     // 67584
#define OFF_W0H   (OFF_A_LO + 256 * ASTR)     // 135168
#define OFF_W0L   (OFF_W0H + 64 * ASTR)       // 152064
#define OFF_W1H   (OFF_W0L + 64 * ASTR)       // 168960
#define OFF_W1L   (OFF_W1H + 64 * ASTR)       // 185856
#define OFF_M     (OFF_W1L + 64 * ASTR)       // 202752
#define OFF_B0    (OFF_M + 3072)              // 205824
#define OFF_B1    (OFF_B0 + 256)
#define OFF_W2    (OFF_B1 + 256)
#define OFF_B2    (OFF_W2 + 256)
#define SMEM_TOTAL (OFF_B2 + 16)              // 206608

extern __shared__ char smem[];

__global__ void __launch_bounds__(512, 1)
mega_kernel(const float* __restrict__ Mmat,
            const float* __restrict__ b0g,
            const float* __restrict__ b1g,
            const float* __restrict__ W2g,
            const float* __restrict__ b2g,
            float* __restrict__ out)
{
    const int tid  = threadIdx.x;
    const int wid  = tid >> 5;
    const int lane = tid & 31;
    const int qr   = lane >> 2;     // 0..7
    const int qc   = lane & 3;      // 0..3

    // ---- stage weights ----
    for (int c = tid; c < 4096; c += 512) {
        int n = c >> 6, kc = c & 63;
        uint32_t off = (uint32_t)(n * ASTR + kc * 4);
        *(uint32_t*)(smem + OFF_W0H + off) = ((const uint32_t*)g_W0T_hi)[c];
        *(uint32_t*)(smem + OFF_W0L + off) = ((const uint32_t*)g_W0T_lo)[c];
    }
    for (int c = tid; c < 2048; c += 512) {
        int n = c >> 5, kc = c & 31;
        uint32_t off = (uint32_t)(n * ASTR + kc * 4);
        *(uint32_t*)(smem + OFF_W1H + off) = ((const uint32_t*)g_W1T_hi)[c];
        *(uint32_t*)(smem + OFF_W1L + off) = ((const uint32_t*)g_W1T_lo)[c];
    }
    float* sM  = (float*)(smem + OFF_M);
    float* sb0 = (float*)(smem + OFF_B0);
    float* sb1 = (float*)(smem + OFF_B1);
    float* sW2 = (float*)(smem + OFF_W2);
    float* sb2 = (float*)(smem + OFF_B2);
    for (int i = tid; i < 768; i += 512) {
        int g = i / 12, r = i % 12;
        sM[i] = Mmat[g * 16 + r];
    }
    if (tid < 64) {
        sb0[tid] = b0g[tid];
        sb1[tid] = b1g[tid];
        sW2[tid] = W2g[tid];
    }
    if (tid == 0) sb2[0] = b2g[0];
    __syncthreads();

    // ---- sampling: 2 threads per point, 32 grids each ----
    const int pbase = blockIdx.x * 256;
    const int row   = tid & 255;
    const int gb    = (tid >> 8) * 32;
    {
        float4 p4 = g_xs4[pbase + row];
        const float px = p4.x, py = p4.y, pz = p4.z;
        char* aHi = smem + OFF_A_HI + row * ASTR;
        char* aLo = smem + OFF_A_LO + row * ASTR;

        for (int gi = 0; gi < 32; gi++) {
            int g = gb + gi;
            const float* Mg = sM + g * 12;
            float tx = fmaf(Mg[0], px, fmaf(Mg[1], py, fmaf(Mg[2],  pz, Mg[3])));
            float ty = fmaf(Mg[4], px, fmaf(Mg[5], py, fmaf(Mg[6],  pz, Mg[7])));
            float tz = fmaf(Mg[8], px, fmaf(Mg[9], py, fmaf(Mg[10], pz, Mg[11])));

            float ix = fmaf(tx, 31.5f, 31.5f);
            float iy = fmaf(ty, 31.5f, 31.5f);
            float iz = fmaf(tz, 31.5f, 31.5f);

            float xf = floorf(ix), yf = floorf(iy), zf = floorf(iz);
            float wx = ix - xf,    wy = iy - yf,    wz = iz - zf;
            int x0 = (int)xf, y0 = (int)yf, z0 = (int)zf;

            float wx0 = (x0 >= 0  && x0 <  RES    ) ? (1.0f - wx) : 0.0f;
            float wx1 = (x0 >= -1 && x0 <  RES - 1) ? wx          : 0.0f;
            float wy0 = (y0 >= 0  && y0 <  RES    ) ? (1.0f - wy) : 0.0f;
            float wy1 = (y0 >= -1 && y0 <  RES - 1) ? wy          : 0.0f;
            float wz0 = (z0 >= 0  && z0 <  RES    ) ? (1.0f - wz) : 0.0f;
            float wz1 = (z0 >= -1 && z0 <  RES - 1) ? wz          : 0.0f;

            int xc0 = min(max(x0, 0), RES - 1),  xc1 = min(max(x0 + 1, 0), RES - 1);
            int yc0 = min(max(y0, 0), RES - 1),  yc1 = min(max(y0 + 1, 0), RES - 1);
            int zc0 = min(max(z0, 0), RES - 1),  zc1 = min(max(z0 + 1, 0), RES - 1);

            const float2* base = g_grids_t + (size_t)g * R3;
            int r00 = (zc0 * RES + yc0) * RES;
            int r01 = (zc0 * RES + yc1) * RES;
            int r10 = (zc1 * RES + yc0) * RES;
            int r11 = (zc1 * RES + yc1) * RES;

            float2 c000 = __ldg(base + r00 + xc0);
            float2 c001 = __ldg(base + r00 + xc1);
            float2 c010 = __ldg(base + r01 + xc0);
            float2 c011 = __ldg(base + r01 + xc1);
            float2 c100 = __ldg(base + r10 + xc0);
            float2 c101 = __ldg(base + r10 + xc1);
            float2 c110 = __ldg(base + r11 + xc0);
            float2 c111 = __ldg(base + r11 + xc1);

            float w00 = wz0 * wy0, w01 = wz0 * wy1;
            float w10 = wz1 * wy0, w11 = wz1 * wy1;
            float w000 = w00 * wx0, w001 = w00 * wx1;
            float w010 = w01 * wx0, w011 = w01 * wx1;
            float w100 = w10 * wx0, w101 = w10 * wx1;
            float w110 = w11 * wx0, w111 = w11 * wx1;

            float f0 = w000 * c000.x;
            float f1 = w000 * c000.y;
            f0 = fmaf(w001, c001.x, f0);  f1 = fmaf(w001, c001.y, f1);
            f0 = fmaf(w010, c010.x, f0);  f1 = fmaf(w010, c010.y, f1);
            f0 = fmaf(w011, c011.x, f0);  f1 = fmaf(w011, c011.y, f1);
            f0 = fmaf(w100, c100.x, f0);  f1 = fmaf(w100, c100.y, f1);
            f0 = fmaf(w101, c101.x, f0);  f1 = fmaf(w101, c101.y, f1);
            f0 = fmaf(w110, c110.x, f0);  f1 = fmaf(w110, c110.y, f1);
            f0 = fmaf(w111, c111.x, f0);  f1 = fmaf(w111, c111.y, f1);

            __nv_bfloat16 h0 = __float2bfloat16(f0);
            __nv_bfloat16 l0 = __float2bfloat16(f0 - __bfloat162float(h0));
            __nv_bfloat16 h1 = __float2bfloat16(f1);
            __nv_bfloat16 l1 = __float2bfloat16(f1 - __bfloat162float(h1));
            *(uint32_t*)(aHi + g * 4) = pack2(h0, h1);
            *(uint32_t*)(aLo + g * 4) = pack2(l0, l1);
        }
    }
    __syncthreads();

    // ---- layer 0 GEMM: warp m-tile = rows 16*wid .. 16*wid+15 ----
    const int mb = wid * 16;
    const uint32_t ar0 = (uint32_t)((mb + qr) * ASTR + qc * 4);
    const uint32_t ar1 = ar0 + 8 * ASTR;

    float acc[8][4];
    #pragma unroll
    for (int nt = 0; nt < 8; nt++)
        #pragma unroll
        for (int j = 0; j < 4; j++) acc[nt][j] = 0.0f;

    #pragma unroll
    for (int kt = 0; kt < 8; kt++) {
        uint32_t ko = kt * 32;
        uint32_t aH0 = *(uint32_t*)(smem + OFF_A_HI + ar0 + ko);
        uint32_t aH1 = *(uint32_t*)(smem + OFF_A_HI + ar1 + ko);
        uint32_t aH2 = *(uint32_t*)(smem + OFF_A_HI + ar0 + ko + 16);
        uint32_t aH3 = *(uint32_t*)(smem + OFF_A_HI + ar1 + ko + 16);
        uint32_t aL0 = *(uint32_t*)(smem + OFF_A_LO + ar0 + ko);
        uint32_t aL1 = *(uint32_t*)(smem + OFF_A_LO + ar1 + ko);
        uint32_t aL2 = *(uint32_t*)(smem + OFF_A_LO + ar0 + ko + 16);
        uint32_t aL3 = *(uint32_t*)(smem + OFF_A_LO + ar1 + ko + 16);
        #pragma unroll
        for (int nt = 0; nt < 8; nt++) {
            uint32_t br = (uint32_t)((nt * 8 + qr) * ASTR + qc * 4 + ko);
            uint32_t bH0 = *(uint32_t*)(smem + OFF_W0H + br);
            uint32_t bH1 = *(uint32_t*)(smem + OFF_W0H + br + 16);
            uint32_t bL0 = *(uint32_t*)(smem + OFF_W0L + br);
            uint32_t bL1 = *(uint32_t*)(smem + OFF_W0L + br + 16);
            mma_bf16(acc[nt], aH0, aH1, aH2, aH3, bH0, bH1);
            mma_bf16(acc[nt], aL0, aL1, aL2, aL3, bH0, bH1);
            mma_bf16(acc[nt], aH0, aH1, aH2, aH3, bL0, bL1);
        }
    }

    // ---- epilogue 0: h = relu(acc + b0), split, store into warp's A rows ----
    __syncwarp();
    {
        int r0 = mb + qr, r1 = r0 + 8;
        #pragma unroll
        for (int nt = 0; nt < 8; nt++) {
            int c0 = nt * 8 + qc * 2;
            float v00 = fmaxf(acc[nt][0] + sb0[c0],     0.0f);
            float v01 = fmaxf(acc[nt][1] + sb0[c0 + 1], 0.0f);
            float v10 = fmaxf(acc[nt][2] + sb0[c0],     0.0f);
            float v11 = fmaxf(acc[nt][3] + sb0[c0 + 1], 0.0f);
            __nv_bfloat16 h00 = __float2bfloat16(v00);
            __nv_bfloat16 h01 = __float2bfloat16(v01);
            __nv_bfloat16 h10 = __float2bfloat16(v10);
            __nv_bfloat16 h11 = __float2bfloat16(v11);
            __nv_bfloat16 l00 = __float2bfloat16(v00 - __bfloat162float(h00));
            __nv_bfloat16 l01 = __float2bfloat16(v01 - __bfloat162float(h01));
            __nv_bfloat16 l10 = __float2bfloat16(v10 - __bfloat162float(h10));
            __nv_bfloat16 l11 = __float2bfloat16(v11 - __bfloat162float(h11));
            uint32_t o0 = (uint32_t)(r0 * ASTR + c0 * 2);
            uint32_t o1 = (uint32_t)(r1 * ASTR + c0 * 2);
            *(uint32_t*)(smem + OFF_A_HI + o0) = pack2(h00, h01);
            *(uint32_t*)(smem + OFF_A_HI + o1) = pack2(h10, h11);
            *(uint32_t*)(smem + OFF_A_LO + o0) = pack2(l00, l01);
            *(uint32_t*)(smem + OFF_A_LO + o1) = pack2(l10, l11);
        }
    }
    __syncwarp();

    // ---- layer 1 GEMM (K=64) ----
    float acc1[8][4];
    #pragma unroll
    for (int nt = 0; nt < 8; nt++)
        #pragma unroll
        for (int j = 0; j < 4; j++) acc1[nt][j] = 0.0f;

    #pragma unroll
    for (int kt = 0; kt < 4; kt++) {
        uint32_t ko = kt * 32;
        uint32_t aH0 = *(uint32_t*)(smem + OFF_A_HI + ar0 + ko);
        uint32_t aH1 = *(uint32_t*)(smem + OFF_A_HI + ar1 + ko);
        uint32_t aH2 = *(uint32_t*)(smem + OFF_A_HI + ar0 + ko + 16);
        uint32_t aH3 = *(uint32_t*)(smem + OFF_A_HI + ar1 + ko + 16);
        uint32_t aL0 = *(uint32_t*)(smem + OFF_A_LO + ar0 + ko);
        uint32_t aL1 = *(uint32_t*)(smem + OFF_A_LO + ar1 + ko);
        uint32_t aL2 = *(uint32_t*)(smem + OFF_A_LO + ar0 + ko + 16);
        uint32_t aL3 = *(uint32_t*)(smem + OFF_A_LO + ar1 + ko + 16);
        #pragma unroll
        for (int nt = 0; nt < 8; nt++) {
            uint32_t br = (uint32_t)((nt * 8 + qr) * ASTR + qc * 4 + ko);
            uint32_t bH0 = *(uint32_t*)(smem + OFF_W1H + br);
            uint32_t bH1 = *(uint32_t*)(smem + OFF_W1H + br + 16);
            uint32_t bL0 = *(uint32_t*)(smem + OFF_W1L + br);
            uint32_t bL1 = *(uint32_t*)(smem + OFF_W1L + br + 16);
            mma_bf16(acc1[nt], aH0, aH1, aH2, aH3, bH0, bH1);
            mma_bf16(acc1[nt], aL0, aL1, aL2, aL3, bH0, bH1);
            mma_bf16(acc1[nt], aH0, aH1, aH2, aH3, bL0, bL1);
        }
    }

    // ---- layer 2: o = relu(acc1 + b1) . W2 + b2, 4-lane reduce ----
    {
        float po0 = 0.0f, po1 = 0.0f;
        #pragma unroll
        for (int nt = 0; nt < 8; nt++) {
            int c0 = nt * 8 + qc * 2;
            float w2a = sW2[c0], w2b = sW2[c0 + 1];
            po0 = fmaf(fmaxf(acc1[nt][0] + sb1[c0],     0.0f), w2a, po0);
            po0 = fmaf(fmaxf(acc1[nt][1] + sb1[c0 + 1], 0.0f), w2b, po0);
            po1 = fmaf(fmaxf(acc1[nt][2] + sb1[c0],     0.0f), w2a, po1);
            po1 = fmaf(fmaxf(acc1[nt][3] + sb1[c0 + 1], 0.0f), w2b, po1);
        }
        po0 += __shfl_xor_sync(0xffffffffu, po0, 1);
        po0 += __shfl_xor_sync(0xffffffffu, po0, 2);
        po1 += __shfl_xor_sync(0xffffffffu, po1, 1);
        po1 += __shfl_xor_sync(0xffffffffu, po1, 2);
        if (qc == 0) {
            int r0 = mb + qr, r1 = r0 + 8;
            float bb = sb2[0];
            out[g_perm[pbase + r0]] = po0 + bb;
            out[g_perm[pbase + r1]] = po1 + bb;
        }
    }
}

// ---------------------------------------------------------------------------
extern "C" void kernel_launch(void* const* d_in, const int* in_sizes, int n_in,
                              void* d_out, int out_size)
{
    const float* x   = (const float*)d_in[0];
    const float* M   = (const float*)d_in[1];
    const float* fg  = (const float*)d_in[2];
    const float* W0  = (const float*)d_in[3];
    const float* b0  = (const float*)d_in[4];
    const float* W1  = (const float*)d_in[5];
    const float* b1  = (const float*)d_in[6];
    const float* W2  = (const float*)d_in[7];
    const float* b2  = (const float*)d_in[8];
    float* out = (float*)d_out;

    prep_weights<<<32, 256>>>(W0, W1);                       // + hist zero
    transpose_grids_kernel<<<(GRIDS * R3 / 4 + 255) / 256, 256>>>(fg);
    keys_kernel<<<NPTS / 256, 256>>>(x);
    scan_kernel<<<1, 1024>>>();
    scatter_kernel<<<NPTS / 256, 256>>>(x);

    cudaFuncSetAttribute(mega_kernel,
                         cudaFuncAttributeMaxDynamicSharedMemorySize, SMEM_TOTAL);
    mega_kernel<<<NPTS / 256, 512, SMEM_TOTAL>>>(M, b0, b1, W2, b2, out);
}

// round 6
// speedup vs baseline: 1.6181x; 1.0006x over previous
#include <cuda_runtime.h>
#include <cuda_bf16.h>
#include <cstdint>
#include <cstddef>

#define GRIDS 64
#define RES 64
#define R3 (RES*RES*RES)
#define NPTS 262144
#define NBINS 32768

// ---------------------------------------------------------------------------
// Device globals
// ---------------------------------------------------------------------------
__device__ float2 g_grids_t[(size_t)GRIDS * R3];           // (g,z,y,x,{f0,f1})
__device__ int g_keys[NPTS];
__device__ int g_perm[NPTS];
__device__ float4 g_xs4[NPTS];                             // permuted points
__device__ __align__(16) int g_hist[NBINS];
__device__ __align__(16) int g_cursor[NBINS];
__device__ __nv_bfloat16 g_W0T_hi[64 * 128];               // [n][k]
__device__ __nv_bfloat16 g_W0T_lo[64 * 128];
__device__ __nv_bfloat16 g_W1T_hi[64 * 64];
__device__ __nv_bfloat16 g_W1T_lo[64 * 64];

// ---------------------------------------------------------------------------
// Kernel: prep weights (bf16 hi/lo, transposed to [n][k]) + zero histogram
// ---------------------------------------------------------------------------
__global__ void prep_weights(const float* __restrict__ W0,
                             const float* __restrict__ W1) {
    int tid = blockIdx.x * blockDim.x + threadIdx.x;   // 8192 threads
    ((int4*)g_hist)[tid] = make_int4(0, 0, 0, 0);      // NBINS/4 = 8192
    {
        int k = tid >> 6, n = tid & 63;
        float w = W0[tid];
        __nv_bfloat16 hi = __float2bfloat16(w);
        g_W0T_hi[n * 128 + k] = hi;
        g_W0T_lo[n * 128 + k] = __float2bfloat16(w - __bfloat162float(hi));
    }
    if (tid < 4096) {
        int k = tid >> 6, n = tid & 63;
        float w = W1[tid];
        __nv_bfloat16 hi = __float2bfloat16(w);
        g_W1T_hi[n * 64 + k] = hi;
        g_W1T_lo[n * 64 + k] = __float2bfloat16(w - __bfloat162float(hi));
    }
}

// ---------------------------------------------------------------------------
// Kernel: transpose grids (G,F,R,R,R) -> (G,R,R,R,F) float2, vectorized
// ---------------------------------------------------------------------------
__global__ void transpose_grids_kernel(const float* __restrict__ grids) {
    int tid = blockIdx.x * blockDim.x + threadIdx.x;   // G*R3/4 threads
    if (tid >= GRIDS * R3 / 4) return;
    int g = tid >> 16;
    int v4 = tid & 65535;
    float4 f0 = *(const float4*)(grids + (size_t)(2 * g) * R3 + (size_t)v4 * 4);
    float4 f1 = *(const float4*)(grids + (size_t)(2 * g + 1) * R3 + (size_t)v4 * 4);
    float4* d4 = (float4*)(g_grids_t + (size_t)g * R3 + (size_t)v4 * 4);
    d4[0] = make_float4(f0.x, f1.x, f0.y, f1.y);
    d4[1] = make_float4(f0.z, f1.z, f0.w, f1.w);
}

// ---------------------------------------------------------------------------
// Morton sort
// ---------------------------------------------------------------------------
__device__ __forceinline__ unsigned part1by2(unsigned v) {
    v = (v * 0x00010001u) & 0xFF0000FFu;
    v = (v * 0x00000101u) & 0x0F00F00Fu;
    v = (v * 0x00000011u) & 0xC30C30C3u;
    v = (v * 0x00000005u) & 0x49249249u;
    return v;
}

__global__ void keys_kernel(const float* __restrict__ x) {
    int i = blockIdx.x * blockDim.x + threadIdx.x;
    if (i >= NPTS) return;
    float px = x[3 * i + 0], py = x[3 * i + 1], pz = x[3 * i + 2];
    int qx = min(max((int)((px + 1.0f) * 16.0f), 0), 31);
    int qy = min(max((int)((py + 1.0f) * 16.0f), 0), 31);
    int qz = min(max((int)((pz + 1.0f) * 16.0f), 0), 31);
    int key = (int)(part1by2((unsigned)qx) | (part1by2((unsigned)qy) << 1)
                  | (part1by2((unsigned)qz) << 2));
    g_keys[i] = key;
    atomicAdd(&g_hist[key], 1);
}

// warp-shuffle hierarchical scan, 1 block x 1024 threads, 32 bins/thread
__global__ void scan_kernel() {
    __shared__ int wsum[32];
    int t = threadIdx.x, lane = t & 31, wid = t >> 5;
    const int4* H = (const int4*)(g_hist + t * 32);
    int v[32];
    int s = 0;
    #pragma unroll
    for (int i = 0; i < 8; i++) {
        int4 q = H[i];
        v[4*i] = q.x; v[4*i+1] = q.y; v[4*i+2] = q.z; v[4*i+3] = q.w;
        s += q.x + q.y + q.z + q.w;
    }
    int incl = s;
    #pragma unroll
    for (int o = 1; o < 32; o <<= 1) {
        int u = __shfl_up_sync(0xffffffffu, incl, o);
        if (lane >= o) incl += u;
    }
    if (lane == 31) wsum[wid] = incl;
    __syncthreads();
    if (wid == 0) {
        int ws = wsum[lane];
        int wincl = ws;
        #pragma unroll
        for (int o = 1; o < 32; o <<= 1) {
            int u = __shfl_up_sync(0xffffffffu, wincl, o);
            if (lane >= o) wincl += u;
        }
        wsum[lane] = wincl - ws;
    }
    __syncthreads();
    int excl = wsum[wid] + incl - s;
    int4* C = (int4*)(g_cursor + t * 32);
    #pragma unroll
    for (int i = 0; i < 8; i++) {
        int c0 = excl;            excl += v[4*i];
        int c1 = excl;            excl += v[4*i+1];
        int c2 = excl;            excl += v[4*i+2];
        int c3 = excl;            excl += v[4*i+3];
        C[i] = make_int4(c0, c1, c2, c3);
    }
}

__global__ void scatter_kernel(const float* __restrict__ x) {
    int i = blockIdx.x * blockDim.x + threadIdx.x;
    if (i >= NPTS) return;
    int p = atomicAdd(&g_cursor[g_keys[i]], 1);
    g_perm[p] = i;
    g_xs4[p] = make_float4(x[3 * i], x[3 * i + 1], x[3 * i + 2], 0.0f);
}

// ---------------------------------------------------------------------------
// mma.sync bf16 helper (baseline PTX, works on plain sm_100 target)
// ---------------------------------------------------------------------------
__device__ __forceinline__ void mma_bf16(float d[4],
                                         uint32_t a0, uint32_t a1,
                                         uint32_t a2, uint32_t a3,
                                         uint32_t b0, uint32_t b1) {
    asm volatile(
        "mma.sync.aligned.m16n8k16.row.col.f32.bf16.bf16.f32 "
        "{%0,%1,%2,%3}, {%4,%5,%6,%7}, {%8,%9}, {%0,%1,%2,%3};"
        : "+f"(d[0]), "+f"(d[1]), "+f"(d[2]), "+f"(d[3])
        : "r"(a0), "r"(a1), "r"(a2), "r"(a3), "r"(b0), "r"(b1));
}

__device__ __forceinline__ uint32_t pack2(__nv_bfloat16 a, __nv_bfloat16 b) {
    __nv_bfloat162 t; t.x = a; t.y = b;
    return *(uint32_t*)&t;
}

// ---------------------------------------------------------------------------
// Mega kernel: sample -> SMEM bf16 hi/lo A -> mma.sync layer0 -> relu ->
// layer1 -> relu -> dot W2. 256 points / CTA, 512 threads, 16 warps.
// SMEM (bytes), A row stride = 264 (128 bf16 padded):
// ---------------------------------------------------------------------------
#define ASTR 264
#define OFF_A_HI  0
#define OFF_A_LO  (OFF_A_HI + 256 * ASTR)     // 67584
#define OFF_W0H   (OFF_A_LO + 256 * ASTR)     // 135168
#define OFF_W0L   (OFF_W0H + 64 * ASTR)       // 152064
#define OFF_W1H   (OFF_W0L + 64 * ASTR)       // 168960
#define OFF_W1L   (OFF_W1H + 64 * ASTR)       // 185856
#define OFF_M     (OFF_W1L + 64 * ASTR)       // 202752
#define OFF_B0    (OFF_M + 3072)              // 205824
#define OFF_B1    (OFF_B0 + 256)
#define OFF_W2    (OFF_B1 + 256)
#define OFF_B2    (OFF_W2 + 256)
#define SMEM_TOTAL (OFF_B2 + 16)              // 206608

extern __shared__ char smem[];

__global__ void __launch_bounds__(512, 1)
mega_kernel(const float* __restrict__ Mmat,
            const float* __restrict__ b0g,
            const float* __restrict__ b1g,
            const float* __restrict__ W2g,
            const float* __restrict__ b2g,
            float* __restrict__ out)
{
    const int tid  = threadIdx.x;
    const int wid  = tid >> 5;
    const int lane = tid & 31;
    const int qr   = lane >> 2;     // 0..7
    const int qc   = lane & 3;      // 0..3

    // ---- stage weights ----
    for (int c = tid; c < 4096; c += 512) {
        int n = c >> 6, kc = c & 63;
        uint32_t off = (uint32_t)(n * ASTR + kc * 4);
        *(uint32_t*)(smem + OFF_W0H + off) = ((const uint32_t*)g_W0T_hi)[c];
        *(uint32_t*)(smem + OFF_W0L + off) = ((const uint32_t*)g_W0T_lo)[c];
    }
    for (int c = tid; c < 2048; c += 512) {
        int n = c >> 5, kc = c & 31;
        uint32_t off = (uint32_t)(n * ASTR + kc * 4);
        *(uint32_t*)(smem + OFF_W1H + off) = ((const uint32_t*)g_W1T_hi)[c];
        *(uint32_t*)(smem + OFF_W1L + off) = ((const uint32_t*)g_W1T_lo)[c];
    }
    float* sM  = (float*)(smem + OFF_M);
    float* sb0 = (float*)(smem + OFF_B0);
    float* sb1 = (float*)(smem + OFF_B1);
    float* sW2 = (float*)(smem + OFF_W2);
    float* sb2 = (float*)(smem + OFF_B2);
    for (int i = tid; i < 768; i += 512) {
        int g = i / 12, r = i % 12;
        sM[i] = Mmat[g * 16 + r];
    }
    if (tid < 64) {
        sb0[tid] = b0g[tid];
        sb1[tid] = b1g[tid];
        sW2[tid] = W2g[tid];
    }
    if (tid == 0) sb2[0] = b2g[0];
    __syncthreads();

    // ---- sampling: 2 threads per point, 32 grids each ----
    const int pbase = blockIdx.x * 256;
    const int row   = tid & 255;
    const int gb    = (tid >> 8) * 32;
    {
        float4 p4 = g_xs4[pbase + row];
        const float px = p4.x, py = p4.y, pz = p4.z;
        char* aHi = smem + OFF_A_HI + row * ASTR;
        char* aLo = smem + OFF_A_LO + row * ASTR;

        for (int gi = 0; gi < 32; gi++) {
            int g = gb + gi;
            const float* Mg = sM + g * 12;
            float tx = fmaf(Mg[0], px, fmaf(Mg[1], py, fmaf(Mg[2],  pz, Mg[3])));
            float ty = fmaf(Mg[4], px, fmaf(Mg[5], py, fmaf(Mg[6],  pz, Mg[7])));
            float tz = fmaf(Mg[8], px, fmaf(Mg[9], py, fmaf(Mg[10], pz, Mg[11])));

            float ix = fmaf(tx, 31.5f, 31.5f);
            float iy = fmaf(ty, 31.5f, 31.5f);
            float iz = fmaf(tz, 31.5f, 31.5f);

            float xf = floorf(ix), yf = floorf(iy), zf = floorf(iz);
            float wx = ix - xf,    wy = iy - yf,    wz = iz - zf;
            int x0 = (int)xf, y0 = (int)yf, z0 = (int)zf;

            float wx0 = (x0 >= 0  && x0 <  RES    ) ? (1.0f - wx) : 0.0f;
            float wx1 = (x0 >= -1 && x0 <  RES - 1) ? wx          : 0.0f;
            float wy0 = (y0 >= 0  && y0 <  RES    ) ? (1.0f - wy) : 0.0f;
            float wy1 = (y0 >= -1 && y0 <  RES - 1) ? wy          : 0.0f;
            float wz0 = (z0 >= 0  && z0 <  RES    ) ? (1.0f - wz) : 0.0f;
            float wz1 = (z0 >= -1 && z0 <  RES - 1) ? wz          : 0.0f;

            int xc0 = min(max(x0, 0), RES - 1),  xc1 = min(max(x0 + 1, 0), RES - 1);
            int yc0 = min(max(y0, 0), RES - 1),  yc1 = min(max(y0 + 1, 0), RES - 1);
            int zc0 = min(max(z0, 0), RES - 1),  zc1 = min(max(z0 + 1, 0), RES - 1);

            const float2* base = g_grids_t + (size_t)g * R3;
            int r00 = (zc0 * RES + yc0) * RES;
            int r01 = (zc0 * RES + yc1) * RES;
            int r10 = (zc1 * RES + yc0) * RES;
            int r11 = (zc1 * RES + yc1) * RES;

            float2 c000 = __ldg(base + r00 + xc0);
            float2 c001 = __ldg(base + r00 + xc1);
            float2 c010 = __ldg(base + r01 + xc0);
            float2 c011 = __ldg(base + r01 + xc1);
            float2 c100 = __ldg(base + r10 + xc0);
            float2 c101 = __ldg(base + r10 + xc1);
            float2 c110 = __ldg(base + r11 + xc0);
            float2 c111 = __ldg(base + r11 + xc1);

            float w00 = wz0 * wy0, w01 = wz0 * wy1;
            float w10 = wz1 * wy0, w11 = wz1 * wy1;
            float w000 = w00 * wx0, w001 = w00 * wx1;
            float w010 = w01 * wx0, w011 = w01 * wx1;
            float w100 = w10 * wx0, w101 = w10 * wx1;
            float w110 = w11 * wx0, w111 = w11 * wx1;

            float f0 = w000 * c000.x;
            float f1 = w000 * c000.y;
            f0 = fmaf(w001, c001.x, f0);  f1 = fmaf(w001, c001.y, f1);
            f0 = fmaf(w010, c010.x, f0);  f1 = fmaf(w010, c010.y, f1);
            f0 = fmaf(w011, c011.x, f0);  f1 = fmaf(w011, c011.y, f1);
            f0 = fmaf(w100, c100.x, f0);  f1 = fmaf(w100, c100.y, f1);
            f0 = fmaf(w101, c101.x, f0);  f1 = fmaf(w101, c101.y, f1);
            f0 = fmaf(w110, c110.x, f0);  f1 = fmaf(w110, c110.y, f1);
            f0 = fmaf(w111, c111.x, f0);  f1 = fmaf(w111, c111.y, f1);

            __nv_bfloat16 h0 = __float2bfloat16(f0);
            __nv_bfloat16 l0 = __float2bfloat16(f0 - __bfloat162float(h0));
            __nv_bfloat16 h1 = __float2bfloat16(f1);
            __nv_bfloat16 l1 = __float2bfloat16(f1 - __bfloat162float(h1));
            *(uint32_t*)(aHi + g * 4) = pack2(h0, h1);
            *(uint32_t*)(aLo + g * 4) = pack2(l0, l1);
        }
    }
    __syncthreads();

    // ---- layer 0 GEMM: warp m-tile = rows 16*wid .. 16*wid+15 ----
    const int mb = wid * 16;
    const uint32_t ar0 = (uint32_t)((mb + qr) * ASTR + qc * 4);
    const uint32_t ar1 = ar0 + 8 * ASTR;

    float acc[8][4];
    #pragma unroll
    for (int nt = 0; nt < 8; nt++)
        #pragma unroll
        for (int j = 0; j < 4; j++) acc[nt][j] = 0.0f;

    #pragma unroll
    for (int kt = 0; kt < 8; kt++) {
        uint32_t ko = kt * 32;
        uint32_t aH0 = *(uint32_t*)(smem + OFF_A_HI + ar0 + ko);
        uint32_t aH1 = *(uint32_t*)(smem + OFF_A_HI + ar1 + ko);
        uint32_t aH2 = *(uint32_t*)(smem + OFF_A_HI + ar0 + ko + 16);
        uint32_t aH3 = *(uint32_t*)(smem + OFF_A_HI + ar1 + ko + 16);
        uint32_t aL0 = *(uint32_t*)(smem + OFF_A_LO + ar0 + ko);
        uint32_t aL1 = *(uint32_t*)(smem + OFF_A_LO + ar1 + ko);
        uint32_t aL2 = *(uint32_t*)(smem + OFF_A_LO + ar0 + ko + 16);
        uint32_t aL3 = *(uint32_t*)(smem + OFF_A_LO + ar1 + ko + 16);
        #pragma unroll
        for (int nt = 0; nt < 8; nt++) {
            uint32_t br = (uint32_t)((nt * 8 + qr) * ASTR + qc * 4 + ko);
            uint32_t bH0 = *(uint32_t*)(smem + OFF_W0H + br);
            uint32_t bH1 = *(uint32_t*)(smem + OFF_W0H + br + 16);
            uint32_t bL0 = *(uint32_t*)(smem + OFF_W0L + br);
            uint32_t bL1 = *(uint32_t*)(smem + OFF_W0L + br + 16);
            mma_bf16(acc[nt], aH0, aH1, aH2, aH3, bH0, bH1);
            mma_bf16(acc[nt], aL0, aL1, aL2, aL3, bH0, bH1);
            mma_bf16(acc[nt], aH0, aH1, aH2, aH3, bL0, bL1);
        }
    }

    // ---- epilogue 0: h = relu(acc + b0), split, store into warp's A rows ----
    __syncwarp();
    {
        int r0 = mb + qr, r1 = r0 + 8;
        #pragma unroll
        for (int nt = 0; nt < 8; nt++) {
            int c0 = nt * 8 + qc * 2;
            float v00 = fmaxf(acc[nt][0] + sb0[c0],     0.0f);
            float v01 = fmaxf(acc[nt][1] + sb0[c0 + 1], 0.0f);
            float v10 = fmaxf(acc[nt][2] + sb0[c0],     0.0f);
            float v11 = fmaxf(acc[nt][3] + sb0[c0 + 1], 0.0f);
            __nv_bfloat16 h00 = __float2bfloat16(v00);
            __nv_bfloat16 h01 = __float2bfloat16(v01);
            __nv_bfloat16 h10 = __float2bfloat16(v10);
            __nv_bfloat16 h11 = __float2bfloat16(v11);
            __nv_bfloat16 l00 = __float2bfloat16(v00 - __bfloat162float(h00));
            __nv_bfloat16 l01 = __float2bfloat16(v01 - __bfloat162float(h01));
            __nv_bfloat16 l10 = __float2bfloat16(v10 - __bfloat162float(h10));
            __nv_bfloat16 l11 = __float2bfloat16(v11 - __bfloat162float(h11));
            uint32_t o0 = (uint32_t)(r0 * ASTR + c0 * 2);
            uint32_t o1 = (uint32_t)(r1 * ASTR + c0 * 2);
            *(uint32_t*)(smem + OFF_A_HI + o0) = pack2(h00, h01);
            *(uint32_t*)(smem + OFF_A_HI + o1) = pack2(h10, h11);
            *(uint32_t*)(smem + OFF_A_LO + o0) = pack2(l00, l01);
            *(uint32_t*)(smem + OFF_A_LO + o1) = pack2(l10, l11);
        }
    }
    __syncwarp();

    // ---- layer 1 GEMM (K=64) ----
    float acc1[8][4];
    #pragma unroll
    for (int nt = 0; nt < 8; nt++)
        #pragma unroll
        for (int j = 0; j < 4; j++) acc1[nt][j] = 0.0f;

    #pragma unroll
    for (int kt = 0; kt < 4; kt++) {
        uint32_t ko = kt * 32;
        uint32_t aH0 = *(uint32_t*)(smem + OFF_A_HI + ar0 + ko);
        uint32_t aH1 = *(uint32_t*)(smem + OFF_A_HI + ar1 + ko);
        uint32_t aH2 = *(uint32_t*)(smem + OFF_A_HI + ar0 + ko + 16);
        uint32_t aH3 = *(uint32_t*)(smem + OFF_A_HI + ar1 + ko + 16);
        uint32_t aL0 = *(uint32_t*)(smem + OFF_A_LO + ar0 + ko);
        uint32_t aL1 = *(uint32_t*)(smem + OFF_A_LO + ar1 + ko);
        uint32_t aL2 = *(uint32_t*)(smem + OFF_A_LO + ar0 + ko + 16);
        uint32_t aL3 = *(uint32_t*)(smem + OFF_A_LO + ar1 + ko + 16);
        #pragma unroll
        for (int nt = 0; nt < 8; nt++) {
            uint32_t br = (uint32_t)((nt * 8 + qr) * ASTR + qc * 4 + ko);
            uint32_t bH0 = *(uint32_t*)(smem + OFF_W1H + br);
            uint32_t bH1 = *(uint32_t*)(smem + OFF_W1H + br + 16);
            uint32_t bL0 = *(uint32_t*)(smem + OFF_W1L + br);
            uint32_t bL1 = *(uint32_t*)(smem + OFF_W1L + br + 16);
            mma_bf16(acc1[nt], aH0, aH1, aH2, aH3, bH0, bH1);
            mma_bf16(acc1[nt], aL0, aL1, aL2, aL3, bH0, bH1);
            mma_bf16(acc1[nt], aH0, aH1, aH2, aH3, bL0, bL1);
        }
    }

    // ---- layer 2: o = relu(acc1 + b1) . W2 + b2, 4-lane reduce ----
    {
        float po0 = 0.0f, po1 = 0.0f;
        #pragma unroll
        for (int nt = 0; nt < 8; nt++) {
            int c0 = nt * 8 + qc * 2;
            float w2a = sW2[c0], w2b = sW2[c0 + 1];
            po0 = fmaf(fmaxf(acc1[nt][0] + sb1[c0],     0.0f), w2a, po0);
            po0 = fmaf(fmaxf(acc1[nt][1] + sb1[c0 + 1], 0.0f), w2b, po0);
            po1 = fmaf(fmaxf(acc1[nt][2] + sb1[c0],     0.0f), w2a, po1);
            po1 = fmaf(fmaxf(acc1[nt][3] + sb1[c0 + 1], 0.0f), w2b, po1);
        }
        po0 += __shfl_xor_sync(0xffffffffu, po0, 1);
        po0 += __shfl_xor_sync(0xffffffffu, po0, 2);
        po1 += __shfl_xor_sync(0xffffffffu, po1, 1);
        po1 += __shfl_xor_sync(0xffffffffu, po1, 2);
        if (qc == 0) {
            int r0 = mb + qr, r1 = r0 + 8;
            float bb = sb2[0];
            out[g_perm[pbase + r0]] = po0 + bb;
            out[g_perm[pbase + r1]] = po1 + bb;
        }
    }
}

// ---------------------------------------------------------------------------
extern "C" void kernel_launch(void* const* d_in, const int* in_sizes, int n_in,
                              void* d_out, int out_size)
{
    const float* x   = (const float*)d_in[0];
    const float* M   = (const float*)d_in[1];
    const float* fg  = (const float*)d_in[2];
    const float* W0  = (const float*)d_in[3];
    const float* b0  = (const float*)d_in[4];
    const float* W1  = (const float*)d_in[5];
    const float* b1  = (const float*)d_in[6];
    const float* W2  = (const float*)d_in[7];
    const float* b2  = (const float*)d_in[8];
    float* out = (float*)d_out;

    prep_weights<<<32, 256>>>(W0, W1);                       // + hist zero
    transpose_grids_kernel<<<(GRIDS * R3 / 4 + 255) / 256, 256>>>(fg);
    keys_kernel<<<NPTS / 256, 256>>>(x);
    scan_kernel<<<1, 1024>>>();
    scatter_kernel<<<NPTS / 256, 256>>>(x);

    cudaFuncSetAttribute(mega_kernel,
                         cudaFuncAttributeMaxDynamicSharedMemorySize, SMEM_TOTAL);
    mega_kernel<<<NPTS / 256, 512, SMEM_TOTAL>>>(M, b0, b1, W2, b2, out);
}